// round 2
// baseline (speedup 1.0000x reference)
#include <cuda_runtime.h>

// QLoRALinear: out[128,11008] = x[128,4096] @ dequant(W) + 2.0 * (x @ A^T) @ B^T
// dequant: w[i,o] = (q[i,o] - zeros[i/128,o]) * scales[i/128,o]
//
// Round 1 baseline: fp32 with packed f32x2 FFMA (2 MACs/instr), tiled,
// x staged in smem (transposed, broadcast reads), weights streamed from HBM.

#define OUTD 11008
#define IND  4096
#define MTOT 128
#define RLORA 16
#define SCALING 2.0f

#define O_TILE 32
#define M_TILE 64
#define K_CHUNK 64
#define XS_PAD 68   // stride % 4 == 0 (float4 alignment), bank spread

// Scratch for LoRA intermediate xa[m][r] = sum_i x[m,i] * A[r,i]
__device__ float g_xa[MTOT * RLORA];

__device__ __forceinline__ unsigned long long pack2(float lo, float hi) {
    unsigned long long r;
    asm("mov.b64 %0, {%1, %2};" : "=l"(r) : "f"(lo), "f"(hi));
    return r;
}

__device__ __forceinline__ void ffma2(unsigned long long &d,
                                      unsigned long long a,
                                      unsigned long long b) {
    // packed fp32x2 fused multiply-add: d = a * b + d (lane-wise)
    asm("fma.rn.f32x2 %0, %1, %2, %0;" : "+l"(d) : "l"(a), "l"(b));
}

// ---------------------------------------------------------------------------
// Kernel 1: xa[m][r] = sum_i x[m][i] * A[r][i]   (128 x 16, tiny)
// ---------------------------------------------------------------------------
__global__ void lora_xa_kernel(const float* __restrict__ x,
                               const float* __restrict__ A) {
    const int m = blockIdx.x;
    const int tid = threadIdx.x;  // 128 threads

    float acc[RLORA];
#pragma unroll
    for (int r = 0; r < RLORA; r++) acc[r] = 0.0f;

    const float* xr = x + m * IND;
    for (int i = tid; i < IND; i += 128) {
        const float xv = xr[i];
#pragma unroll
        for (int r = 0; r < RLORA; r++)
            acc[r] = fmaf(xv, A[r * IND + i], acc[r]);
    }

    __shared__ float sred[RLORA][129];
#pragma unroll
    for (int r = 0; r < RLORA; r++) sred[r][tid] = acc[r];
    __syncthreads();

    if (tid < RLORA) {
        float s = 0.0f;
        for (int i = 0; i < 128; i++) s += sred[tid][i];
        g_xa[m * RLORA + tid] = s;
    }
}

// ---------------------------------------------------------------------------
// Kernel 2: main GEMM with int4-code dequant + LoRA epilogue
// Block: 64 threads = 32 (o lanes) x 2 (m groups of 32 rows each)
// Grid:  (11008/32, 128/64) = (344, 2)
// ---------------------------------------------------------------------------
__global__ __launch_bounds__(64) void qlora_main_kernel(
    const float* __restrict__ x,
    const int*   __restrict__ W,
    const int*   __restrict__ zeros,
    const float* __restrict__ scales,
    const float* __restrict__ loraB,
    float*       __restrict__ out)
{
    __shared__ __align__(16) float xs[K_CHUNK][XS_PAD];

    const int tid = threadIdx.x;
    const int tx  = tid & 31;          // output lane
    const int ty  = tid >> 5;          // 0..1 -> which 32-row group
    const int o   = blockIdx.x * O_TILE + tx;
    const int mb  = blockIdx.y * M_TILE;

    // 32 rows per thread as 16 packed f32x2 accumulators
    unsigned long long acc2[16];
#pragma unroll
    for (int p = 0; p < 16; p++) acc2[p] = 0ull;

#pragma unroll 1
    for (int kc = 0; kc < IND / K_CHUNK; kc++) {
        const int k0 = kc * K_CHUNK;

        // Stage x chunk, transposed: xs[kk][m] = x[mb+m][k0+kk]
        // thread t handles kk = t for all 64 m rows (coalesced over t)
#pragma unroll 8
        for (int m = 0; m < M_TILE; m++)
            xs[tid][m] = x[(mb + m) * IND + k0 + tid];
        __syncthreads();

        const int g = k0 >> 7;  // quant group (128 k per group)
        const float sv = scales[g * OUTD + o];
        const float zs = (float)zeros[g * OUTD + o] * sv;
        const int* Wp = W + k0 * OUTD + o;

#pragma unroll 8
        for (int kk = 0; kk < K_CHUNK; kk++) {
            const int q = Wp[kk * OUTD];
            const float wv = fmaf((float)q, sv, -zs);
            const unsigned long long w2 = pack2(wv, wv);

            const float* xr = &xs[kk][ty * 32];
#pragma unroll
            for (int j = 0; j < 8; j++) {
                const ulonglong2 xv = *(const ulonglong2*)(xr + 4 * j);
                ffma2(acc2[2 * j],     xv.x, w2);
                ffma2(acc2[2 * j + 1], xv.y, w2);
            }
        }
        __syncthreads();
    }

    // ---- Epilogue: add LoRA term and store ----
    const float4 b0 = *(const float4*)&loraB[o * RLORA + 0];
    const float4 b1 = *(const float4*)&loraB[o * RLORA + 4];
    const float4 b2 = *(const float4*)&loraB[o * RLORA + 8];
    const float4 b3 = *(const float4*)&loraB[o * RLORA + 12];
    float Bv[16] = {b0.x, b0.y, b0.z, b0.w, b1.x, b1.y, b1.z, b1.w,
                    b2.x, b2.y, b2.z, b2.w, b3.x, b3.y, b3.z, b3.w};

#pragma unroll
    for (int p = 0; p < 16; p++) {
        const int m0 = mb + ty * 32 + 2 * p;
        union { unsigned long long u; float2 f; } cv;
        cv.u = acc2[p];

        float l0 = 0.0f, l1 = 0.0f;
#pragma unroll
        for (int r = 0; r < RLORA; r++) {
            l0 = fmaf(g_xa[m0 * RLORA + r],       Bv[r], l0);
            l1 = fmaf(g_xa[(m0 + 1) * RLORA + r], Bv[r], l1);
        }
        out[m0 * OUTD + o]       = cv.f.x + SCALING * l0;
        out[(m0 + 1) * OUTD + o] = cv.f.y + SCALING * l1;
    }
}

// ---------------------------------------------------------------------------
extern "C" void kernel_launch(void* const* d_in, const int* in_sizes, int n_in,
                              void* d_out, int out_size) {
    const float* x      = (const float*)d_in[0];   // [128, 4096]
    const int*   W      = (const int*)  d_in[1];   // [4096, 11008] int4 codes
    const int*   zeros  = (const int*)  d_in[2];   // [32, 11008]
    const float* scales = (const float*)d_in[3];   // [32, 11008]
    const float* loraA  = (const float*)d_in[4];   // [16, 4096]
    const float* loraB  = (const float*)d_in[5];   // [11008, 16]
    float* out = (float*)d_out;                    // [128, 11008]

    lora_xa_kernel<<<MTOT, 128>>>(x, loraA);

    dim3 grid(OUTD / O_TILE, MTOT / M_TILE);
    qlora_main_kernel<<<grid, 64>>>(x, W, zeros, scales, loraB, out);
}

// round 3
// speedup vs baseline: 1.7479x; 1.7479x over previous
#include <cuda_runtime.h>

// QLoRALinear: out[128,11008] = x[128,4096] @ dequant(W) + 2.0 * (x @ A^T) @ B^T
// dequant: w[k,o] = (q[k,o] - zeros[k/128,o]) * scales[k/128,o]
//
// Round 2: smem-tiled fp32x2 GEMM.
//   main kernel: block tile 128m x 128o x 512k (K split 8 ways), 256 threads,
//   thread tile 8m x 8o (32 FFMA2 / k-step), W dequantized into smem once per
//   32-k chunk, x transposed into smem. Partials to device scratch.
//   reduce kernel: sum 8 partials + LoRA epilogue.

#define OUTD 11008
#define IND  4096
#define MTOT 128
#define RLORA 16
#define SCALING 2.0f

#define KSPLIT 8
#define KSLICE (IND / KSPLIT)       // 512
#define K_CHUNK 32
#define NCHUNK (KSLICE / K_CHUNK)   // 16
#define O_TILE 128
#define GROUPS_PER_SLICE (KSLICE / 128)  // 4

// xs: [K_CHUNK][132] floats (pad -> 33 x 16B row stride, odd)
#define XS_STRIDE 132
// ws: 16 o-blocks, each [K_CHUNK][8] floats padded to 260 floats (65 x 16B, odd)
#define WS_BLK 260

// device scratch
__device__ float g_partial[KSPLIT * MTOT * OUTD];   // 45 MB
__device__ float g_xa[MTOT * RLORA];

__device__ __forceinline__ unsigned long long pack2(float v) {
    unsigned long long r;
    asm("mov.b64 %0, {%1, %1};" : "=l"(r) : "f"(v));
    return r;
}
__device__ __forceinline__ void ffma2(unsigned long long &d,
                                      unsigned long long a,
                                      unsigned long long b) {
    asm("fma.rn.f32x2 %0, %1, %2, %0;" : "+l"(d) : "l"(a), "l"(b));
}

// ---------------------------------------------------------------------------
// xa[m][r] = sum_i x[m][i] * A[r][i]
// ---------------------------------------------------------------------------
__global__ void lora_xa_kernel(const float* __restrict__ x,
                               const float* __restrict__ A) {
    const int m = blockIdx.x;
    const int tid = threadIdx.x;  // 128

    float acc[RLORA];
#pragma unroll
    for (int r = 0; r < RLORA; r++) acc[r] = 0.0f;

    const float* xr = x + m * IND;
    for (int i = tid; i < IND; i += 128) {
        const float xv = xr[i];
#pragma unroll
        for (int r = 0; r < RLORA; r++)
            acc[r] = fmaf(xv, A[r * IND + i], acc[r]);
    }

    __shared__ float sred[RLORA][129];
#pragma unroll
    for (int r = 0; r < RLORA; r++) sred[r][tid] = acc[r];
    __syncthreads();

    if (tid < RLORA) {
        float s = 0.0f;
        for (int i = 0; i < 128; i++) s += sred[tid][i];
        g_xa[m * RLORA + tid] = s;
    }
}

// ---------------------------------------------------------------------------
// Main GEMM: grid (86, 8), block 256.
//   blockIdx.x -> o tile (128 outs), blockIdx.y -> k slice (512 k)
//   thread (to = tid%16, tm = tid/16) -> outs [8*tm..+8) x [8*to..+8)
// ---------------------------------------------------------------------------
__global__ __launch_bounds__(256, 2) void qlora_main_kernel(
    const float* __restrict__ x,
    const int*   __restrict__ W,
    const int*   __restrict__ zeros,
    const float* __restrict__ scales)
{
    __shared__ __align__(16) float xs[K_CHUNK][XS_STRIDE];   // 16.9 KB
    __shared__ __align__(16) float ws[16 * WS_BLK];          // 16.6 KB
    __shared__ __align__(16) float2 szs[GROUPS_PER_SLICE][O_TILE]; // 4 KB

    const int tid   = threadIdx.x;
    const int to    = tid & 15;
    const int tm    = tid >> 4;
    const int obase = blockIdx.x * O_TILE;
    const int ks    = blockIdx.y;
    const int kbase = ks * KSLICE;

    // preload (scale, zero*scale) for the 4 quant groups of this k-slice
    const int gbase = ks * GROUPS_PER_SLICE;
    for (int idx = tid; idx < GROUPS_PER_SLICE * O_TILE; idx += 256) {
        const int g = idx >> 7;
        const int o = idx & 127;
        const float s = scales[(gbase + g) * OUTD + obase + o];
        const float z = (float)zeros[(gbase + g) * OUTD + obase + o];
        szs[g][o] = make_float2(s, z * s);
    }

    unsigned long long acc[4][8];
#pragma unroll
    for (int p = 0; p < 4; p++)
#pragma unroll
        for (int o = 0; o < 8; o++) acc[p][o] = 0ull;

    // staging thread mapping
    const int w_kl = tid >> 3;        // 0..31  k row within chunk
    const int w_oi = tid & 7;         // 0..7   16-o block
    const int x_m  = tid >> 1;        // 0..127 m row
    const int x_kh = tid & 1;         // 0..1   16-k half

    const int ws_off = to * WS_BLK;   // this thread's o-block in ws
    const int m0 = 8 * tm;

    __syncthreads();  // szs ready

#pragma unroll 1
    for (int c = 0; c < NCHUNK; c++) {
        const int k0 = kbase + c * K_CHUNK;
        const int kg = c >> 2;   // group within slice (32k chunk / 128k group)

        // ---- stage W: load 32 x 128 int codes, dequant, store o-block layout
        {
            const int* Wp = W + (k0 + w_kl) * OUTD + obase + w_oi * 16;
#pragma unroll
            for (int q = 0; q < 4; q++) {
                const int4 v = *(const int4*)(Wp + 4 * q);
                const int ol = w_oi * 16 + 4 * q;
                const float4 sz0 = *(const float4*)&szs[kg][ol];      // s0,zs0,s1,zs1
                const float4 sz1 = *(const float4*)&szs[kg][ol + 2];  // s2,zs2,s3,zs3
                float4 wv;
                wv.x = fmaf((float)v.x, sz0.x, -sz0.y);
                wv.y = fmaf((float)v.y, sz0.z, -sz0.w);
                wv.z = fmaf((float)v.z, sz1.x, -sz1.y);
                wv.w = fmaf((float)v.w, sz1.z, -sz1.w);
                *(float4*)&ws[(2 * w_oi + (q >> 1)) * WS_BLK + w_kl * 8 + (q & 1) * 4] = wv;
            }
        }

        // ---- stage x transposed: xs[kk][m]
        {
            const float* xp = x + x_m * IND + k0 + x_kh * 16;
#pragma unroll
            for (int q = 0; q < 4; q++) {
                const float4 v = *(const float4*)(xp + 4 * q);
                const int kk = x_kh * 16 + 4 * q;
                xs[kk + 0][x_m] = v.x;
                xs[kk + 1][x_m] = v.y;
                xs[kk + 2][x_m] = v.z;
                xs[kk + 3][x_m] = v.w;
            }
        }
        __syncthreads();

        // ---- compute 32 k-steps
#pragma unroll 8
        for (int kk = 0; kk < K_CHUNK; kk++) {
            const ulonglong2 xp01 = *(const ulonglong2*)&xs[kk][m0];     // (m0,m0+1),(m0+2,m0+3)
            const ulonglong2 xp23 = *(const ulonglong2*)&xs[kk][m0 + 4]; // (m0+4..m0+7)
            const float4 w0 = *(const float4*)&ws[ws_off + kk * 8];
            const float4 w1 = *(const float4*)&ws[ws_off + kk * 8 + 4];

            unsigned long long wd[8];
            wd[0] = pack2(w0.x); wd[1] = pack2(w0.y);
            wd[2] = pack2(w0.z); wd[3] = pack2(w0.w);
            wd[4] = pack2(w1.x); wd[5] = pack2(w1.y);
            wd[6] = pack2(w1.z); wd[7] = pack2(w1.w);

#pragma unroll
            for (int o = 0; o < 8; o++) {
                ffma2(acc[0][o], xp01.x, wd[o]);
                ffma2(acc[1][o], xp01.y, wd[o]);
                ffma2(acc[2][o], xp23.x, wd[o]);
                ffma2(acc[3][o], xp23.y, wd[o]);
            }
        }
        __syncthreads();
    }

    // ---- write partial tile
    float* pp = g_partial + ks * (MTOT * OUTD);
    const int og = obase + 8 * to;
#pragma unroll
    for (int p = 0; p < 4; p++) {
        union { unsigned long long u; float2 f; } cv[8];
#pragma unroll
        for (int o = 0; o < 8; o++) cv[o].u = acc[p][o];

        const int r0 = m0 + 2 * p;
        float4 a = make_float4(cv[0].f.x, cv[1].f.x, cv[2].f.x, cv[3].f.x);
        float4 b = make_float4(cv[4].f.x, cv[5].f.x, cv[6].f.x, cv[7].f.x);
        *(float4*)&pp[r0 * OUTD + og]     = a;
        *(float4*)&pp[r0 * OUTD + og + 4] = b;
        a = make_float4(cv[0].f.y, cv[1].f.y, cv[2].f.y, cv[3].f.y);
        b = make_float4(cv[4].f.y, cv[5].f.y, cv[6].f.y, cv[7].f.y);
        *(float4*)&pp[(r0 + 1) * OUTD + og]     = a;
        *(float4*)&pp[(r0 + 1) * OUTD + og + 4] = b;
    }
}

// ---------------------------------------------------------------------------
// Reduce partials + LoRA epilogue.
// grid (11, 128), block 256; each thread one float4 of one m-row.
// ---------------------------------------------------------------------------
__global__ __launch_bounds__(256) void reduce_kernel(
    const float* __restrict__ loraB,
    float*       __restrict__ out)
{
    const int m = blockIdx.y;
    const int oc = blockIdx.x * 256 + threadIdx.x;   // float4 index within row

    __shared__ float sxa[RLORA];
    if (threadIdx.x < RLORA) sxa[threadIdx.x] = g_xa[m * RLORA + threadIdx.x];
    __syncthreads();

    if (oc >= OUTD / 4) return;
    const int o = 4 * oc;

    float4 s = make_float4(0.f, 0.f, 0.f, 0.f);
#pragma unroll
    for (int p = 0; p < KSPLIT; p++) {
        const float4 v = *(const float4*)&g_partial[p * (MTOT * OUTD) + m * OUTD + o];
        s.x += v.x; s.y += v.y; s.z += v.z; s.w += v.w;
    }

    float l[4] = {0.f, 0.f, 0.f, 0.f};
#pragma unroll
    for (int j = 0; j < 4; j++) {
        const float* Bp = loraB + (o + j) * RLORA;
#pragma unroll
        for (int r = 0; r < RLORA; r++)
            l[j] = fmaf(sxa[r], Bp[r], l[j]);
    }

    s.x += SCALING * l[0];
    s.y += SCALING * l[1];
    s.z += SCALING * l[2];
    s.w += SCALING * l[3];
    *(float4*)&out[m * OUTD + o] = s;
}

// ---------------------------------------------------------------------------
extern "C" void kernel_launch(void* const* d_in, const int* in_sizes, int n_in,
                              void* d_out, int out_size) {
    const float* x      = (const float*)d_in[0];   // [128, 4096]
    const int*   W      = (const int*)  d_in[1];   // [4096, 11008]
    const int*   zeros  = (const int*)  d_in[2];   // [32, 11008]
    const float* scales = (const float*)d_in[3];   // [32, 11008]
    const float* loraA  = (const float*)d_in[4];   // [16, 4096]
    const float* loraB  = (const float*)d_in[5];   // [11008, 16]
    float* out = (float*)d_out;                    // [128, 11008]

    lora_xa_kernel<<<MTOT, 128>>>(x, loraA);

    dim3 grid(OUTD / O_TILE, KSPLIT);
    qlora_main_kernel<<<grid, 256>>>(x, W, zeros, scales);

    dim3 rgrid((OUTD / 4 + 255) / 256, MTOT);
    reduce_kernel<<<rgrid, 256>>>(loraB, out);
}

// round 5
// speedup vs baseline: 2.9374x; 1.6805x over previous
#include <cuda_runtime.h>
#include <cuda_bf16.h>
#include <stdint.h>

// QLoRALinear: out[128,11008] = x @ dequant_int4(W) + 2*(x@A^T)@B^T
// Round 5: mma.sync m16n8k16 bf16 (baseline PTX; tcgen05 not supported by the
// harness's compute_103 PTX target). 3-term hi/lo split in bf16, fp32 accum.

#define OUTD 11008
#define IND  4096
#define MTOT 128
#define RLORA 16

#define NTILE 64           // o per block
#define KSPLIT 2
#define KC 64              // k per chunk
#define NCH (IND / KSPLIT / KC)   // 32 chunks per block
#define NCHUNK_TOT (IND / KC)     // 64 tiles in prep layout
#define ROWH 72            // halves per smem/tile row (64 data + 8 pad) = 144B

// smem offsets in halves, per buffer
#define XH_OFF 0
#define XL_OFF 9216        // 128*72
#define WH_OFF 18432
#define WL_OFF 23040       // + 64*72
#define BUF_H  27648       // halves per buffer
#define SMEM_BYTES (2 * BUF_H * 2)   // 110592

// ---- device scratch ----
// x hi/lo pre-tiled: [chunk][m 0..127][72 halves] (pad incl.), 1.125 MB each
__device__ __align__(16) uint16_t g_xh[NCHUNK_TOT * MTOT * ROWH];
__device__ __align__(16) uint16_t g_xl[NCHUNK_TOT * MTOT * ROWH];
__device__ __align__(16) float    g_xa[MTOT * RLORA];            // pre-scaled x @ A^T * 2
__device__ float g_partial[KSPLIT * MTOT * OUTD];                // 11.3 MB

// ---------------------------------------------------------------------------
__device__ __forceinline__ uint32_t pack_bf16x2(float lo, float hi) {
    uint32_t r;
    asm("cvt.rn.bf16x2.f32 %0, %1, %2;" : "=r"(r) : "f"(hi), "f"(lo));
    return r;
}
__device__ __forceinline__ uint32_t smem_u32(const void* p) {
    uint32_t a;
    asm("{ .reg .u64 t; cvta.to.shared.u64 t, %1; cvt.u32.u64 %0, t; }"
        : "=r"(a) : "l"(p));
    return a;
}
__device__ __forceinline__ void cp16(uint32_t dst, const void* src) {
    asm volatile("cp.async.cg.shared.global [%0], [%1], 16;"
                 :: "r"(dst), "l"(src) : "memory");
}
__device__ __forceinline__ void mma16816(float* d, const uint32_t* a,
                                         const uint32_t* b) {
    asm volatile(
        "mma.sync.aligned.m16n8k16.row.col.f32.bf16.bf16.f32 "
        "{%0,%1,%2,%3}, {%4,%5,%6,%7}, {%8,%9}, {%0,%1,%2,%3};"
        : "+f"(d[0]), "+f"(d[1]), "+f"(d[2]), "+f"(d[3])
        : "r"(a[0]), "r"(a[1]), "r"(a[2]), "r"(a[3]), "r"(b[0]), "r"(b[1]));
}

// ---------------------------------------------------------------------------
// Prep: split x into bf16 hi/lo tile images + xa = 2*(x @ A^T)
// grid = 128 (m), 256 threads (16 k each)
// ---------------------------------------------------------------------------
__global__ __launch_bounds__(256) void prep_kernel(const float* __restrict__ x,
                                                   const float* __restrict__ A) {
    const int m = blockIdx.x;
    const int t = threadIdx.x;
    const int wid = t >> 5, lane = t & 31;
    const int k0 = t * 16;

    float xv[16];
#pragma unroll
    for (int q = 0; q < 4; q++)
        *(float4*)&xv[4 * q] = *(const float4*)(x + (size_t)m * IND + k0 + 4 * q);

    uint32_t hw[8], lw[8];
#pragma unroll
    for (int p = 0; p < 8; p++) {
        const float f0 = xv[2 * p], f1 = xv[2 * p + 1];
        const uint32_t h2 = pack_bf16x2(f0, f1);
        const float b0 = __uint_as_float(h2 << 16);
        const float b1 = __uint_as_float(h2 & 0xffff0000u);
        hw[p] = h2;
        lw[p] = pack_bf16x2(f0 - b0, f1 - b1);
    }
    // tile destination: chunk = t/4, 16 halves at row offset (t%4)*16
    const int chunk = t >> 2;
    const size_t base = ((size_t)chunk * MTOT + m) * ROWH + (t & 3) * 16;
    uint4* ph = (uint4*)(g_xh + base);
    uint4* pl = (uint4*)(g_xl + base);
    ph[0] = make_uint4(hw[0], hw[1], hw[2], hw[3]);
    ph[1] = make_uint4(hw[4], hw[5], hw[6], hw[7]);
    pl[0] = make_uint4(lw[0], lw[1], lw[2], lw[3]);
    pl[1] = make_uint4(lw[4], lw[5], lw[6], lw[7]);

    // xa
    float acc[RLORA];
#pragma unroll
    for (int r = 0; r < RLORA; r++) acc[r] = 0.0f;
#pragma unroll
    for (int r = 0; r < RLORA; r++) {
        const float* Ar = A + (size_t)r * IND + k0;
#pragma unroll
        for (int q = 0; q < 4; q++) {
            const float4 a4 = *(const float4*)(Ar + 4 * q);
            acc[r] = fmaf(xv[4 * q + 0], a4.x, acc[r]);
            acc[r] = fmaf(xv[4 * q + 1], a4.y, acc[r]);
            acc[r] = fmaf(xv[4 * q + 2], a4.z, acc[r]);
            acc[r] = fmaf(xv[4 * q + 3], a4.w, acc[r]);
        }
    }
#pragma unroll
    for (int r = 0; r < RLORA; r++)
#pragma unroll
        for (int off = 16; off > 0; off >>= 1)
            acc[r] += __shfl_xor_sync(0xffffffffu, acc[r], off);

    __shared__ float red[8][RLORA];
    if (lane == 0)
#pragma unroll
        for (int r = 0; r < RLORA; r++) red[wid][r] = acc[r];
    __syncthreads();
    if (t < RLORA) {
        float s = 0.0f;
#pragma unroll
        for (int w = 0; w < 8; w++) s += red[w][t];
        g_xa[m * RLORA + t] = 2.0f * s;
    }
}

// ---------------------------------------------------------------------------
// Main GEMM: grid (172, 2), 256 threads (8 warps; warp tile 32m x 32o)
// ---------------------------------------------------------------------------
__global__ __launch_bounds__(256, 2) void qmain_kernel(
    const int*   __restrict__ W,
    const int*   __restrict__ zeros,
    const float* __restrict__ scales)
{
    extern __shared__ __align__(16) uint16_t sm[];
    const uint32_t smb = smem_u32(sm);

    const int t = threadIdx.x;
    const int lane = t & 31;
    const int wid = t >> 5;
    const int wm = wid & 3;           // m group (32 rows)
    const int wo = wid >> 2;          // o group (32 cols)
    const int obase = blockIdx.x * NTILE;
    const int kh = blockIdx.y;

    // staging mapping
    const int so  = t & 63;           // W: o lane
    const int skq = t >> 6;           // W: 16-k quarter
    const int xrow = t >> 1;          // x: m row
    const int xhalf = t & 1;          // x: 32-half (64B) segment

    float acc[2][4][4];
#pragma unroll
    for (int mt = 0; mt < 2; mt++)
#pragma unroll
        for (int ot = 0; ot < 4; ot++)
#pragma unroll
            for (int i = 0; i < 4; i++) acc[mt][ot][i] = 0.0f;

    int buf = 0;

    // ---- staging helpers (inlined by macro-ish lambdas) ----
    auto stage = [&](int b, int c) {
        const int ck = kh * NCH + c;          // global chunk
        const int k0 = ck * KC;
        // x tiles via cp.async (copies the pre-swizzled tile image)
        {
            const size_t src = ((size_t)ck * MTOT + xrow) * ROWH + xhalf * 32;
            const uint32_t dxh = smb + (b * BUF_H + XH_OFF + xrow * ROWH + xhalf * 32) * 2;
            const uint32_t dxl = smb + (b * BUF_H + XL_OFF + xrow * ROWH + xhalf * 32) * 2;
#pragma unroll
            for (int j = 0; j < 4; j++) {
                cp16(dxh + j * 16, g_xh + src + j * 8);
                cp16(dxl + j * 16, g_xl + src + j * 8);
            }
            asm volatile("cp.async.commit_group;" ::: "memory");
        }
        // W dequant + split
        {
            const int g = k0 >> 7;
            const int oabs = obase + so;
            const float s  = scales[(size_t)g * OUTD + oabs];
            const float zs = (float)zeros[(size_t)g * OUTD + oabs] * s;
            const int* Wp = W + (size_t)(k0 + skq * 16) * OUTD + oabs;
            uint32_t hp[8], lp[8];
#pragma unroll
            for (int p = 0; p < 8; p++) {
                const int q0 = Wp[(size_t)(2 * p) * OUTD];
                const int q1 = Wp[(size_t)(2 * p + 1) * OUTD];
                const float f0 = fmaf((float)q0, s, -zs);
                const float f1 = fmaf((float)q1, s, -zs);
                const uint32_t h2 = pack_bf16x2(f0, f1);
                hp[p] = h2;
                lp[p] = pack_bf16x2(f0 - __uint_as_float(h2 << 16),
                                    f1 - __uint_as_float(h2 & 0xffff0000u));
            }
            uint16_t* wh = sm + b * BUF_H + WH_OFF + so * ROWH + skq * 16;
            uint16_t* wl = sm + b * BUF_H + WL_OFF + so * ROWH + skq * 16;
            ((uint4*)wh)[0] = make_uint4(hp[0], hp[1], hp[2], hp[3]);
            ((uint4*)wh)[1] = make_uint4(hp[4], hp[5], hp[6], hp[7]);
            ((uint4*)wl)[0] = make_uint4(lp[0], lp[1], lp[2], lp[3]);
            ((uint4*)wl)[1] = make_uint4(lp[4], lp[5], lp[6], lp[7]);
        }
    };

    // prologue
    stage(0, 0);
    asm volatile("cp.async.wait_group 0;" ::: "memory");
    __syncthreads();

    const int arow = (lane >> 2);
    const int acol = (lane & 3) * 2;

#pragma unroll 1
    for (int c = 0; c < NCH; c++) {
        if (c + 1 < NCH) stage(buf ^ 1, c + 1);

        const uint16_t* xh = sm + buf * BUF_H + XH_OFF;
        const uint16_t* xl = sm + buf * BUF_H + XL_OFF;
        const uint16_t* wh = sm + buf * BUF_H + WH_OFF;
        const uint16_t* wl = sm + buf * BUF_H + WL_OFF;

#pragma unroll
        for (int ks = 0; ks < KC; ks += 16) {
            uint32_t ah[2][4], al[2][4];
#pragma unroll
            for (int mt = 0; mt < 2; mt++) {
                const uint16_t* xr = xh + (wm * 32 + mt * 16 + arow) * ROWH + ks + acol;
                ah[mt][0] = *(const uint32_t*)(xr);
                ah[mt][1] = *(const uint32_t*)(xr + 8 * ROWH);
                ah[mt][2] = *(const uint32_t*)(xr + 8);
                ah[mt][3] = *(const uint32_t*)(xr + 8 * ROWH + 8);
                const uint16_t* xr2 = xl + (wm * 32 + mt * 16 + arow) * ROWH + ks + acol;
                al[mt][0] = *(const uint32_t*)(xr2);
                al[mt][1] = *(const uint32_t*)(xr2 + 8 * ROWH);
                al[mt][2] = *(const uint32_t*)(xr2 + 8);
                al[mt][3] = *(const uint32_t*)(xr2 + 8 * ROWH + 8);
            }
#pragma unroll
            for (int ot = 0; ot < 4; ot++) {
                const uint16_t* wr = wh + (wo * 32 + ot * 8 + arow) * ROWH + ks + acol;
                uint32_t bh[2] = { *(const uint32_t*)(wr), *(const uint32_t*)(wr + 8) };
                const uint16_t* wr2 = wl + (wo * 32 + ot * 8 + arow) * ROWH + ks + acol;
                uint32_t bl[2] = { *(const uint32_t*)(wr2), *(const uint32_t*)(wr2 + 8) };
#pragma unroll
                for (int mt = 0; mt < 2; mt++) {
                    mma16816(acc[mt][ot], ah[mt], bh);
                    mma16816(acc[mt][ot], al[mt], bh);
                    mma16816(acc[mt][ot], ah[mt], bl);
                }
            }
        }

        asm volatile("cp.async.wait_group 0;" ::: "memory");
        __syncthreads();
        buf ^= 1;
    }

    // ---- store partials ----
    float* pp = g_partial + (size_t)kh * MTOT * OUTD;
#pragma unroll
    for (int mt = 0; mt < 2; mt++) {
        const int r0 = wm * 32 + mt * 16 + arow;
#pragma unroll
        for (int ot = 0; ot < 4; ot++) {
            const int cabs = obase + wo * 32 + ot * 8 + acol;
            *(float2*)&pp[(size_t)r0 * OUTD + cabs] =
                make_float2(acc[mt][ot][0], acc[mt][ot][1]);
            *(float2*)&pp[(size_t)(r0 + 8) * OUTD + cabs] =
                make_float2(acc[mt][ot][2], acc[mt][ot][3]);
        }
    }
}

// ---------------------------------------------------------------------------
// Reduce partials + LoRA epilogue (xa pre-scaled).
// ---------------------------------------------------------------------------
__global__ __launch_bounds__(256) void reduce_kernel(
    const float* __restrict__ loraB,
    float*       __restrict__ out)
{
    const int m = blockIdx.y;
    const int oc = blockIdx.x * 256 + threadIdx.x;

    __shared__ float sxa[RLORA];
    if (threadIdx.x < RLORA) sxa[threadIdx.x] = g_xa[m * RLORA + threadIdx.x];
    __syncthreads();

    if (oc >= OUTD / 4) return;
    const int o = 4 * oc;

    float4 s = make_float4(0.f, 0.f, 0.f, 0.f);
#pragma unroll
    for (int p = 0; p < KSPLIT; p++) {
        const float4 v = *(const float4*)&g_partial[(size_t)p * MTOT * OUTD +
                                                    (size_t)m * OUTD + o];
        s.x += v.x; s.y += v.y; s.z += v.z; s.w += v.w;
    }
    float l[4] = {0.f, 0.f, 0.f, 0.f};
#pragma unroll
    for (int j = 0; j < 4; j++) {
        const float* Bp = loraB + (size_t)(o + j) * RLORA;
#pragma unroll
        for (int r = 0; r < RLORA; r++)
            l[j] = fmaf(sxa[r], Bp[r], l[j]);
    }
    s.x += l[0]; s.y += l[1]; s.z += l[2]; s.w += l[3];
    *(float4*)&out[(size_t)m * OUTD + o] = s;
}

// ---------------------------------------------------------------------------
extern "C" void kernel_launch(void* const* d_in, const int* in_sizes, int n_in,
                              void* d_out, int out_size) {
    const float* x      = (const float*)d_in[0];
    const int*   W      = (const int*)  d_in[1];
    const int*   zeros  = (const int*)  d_in[2];
    const float* scales = (const float*)d_in[3];
    const float* loraA  = (const float*)d_in[4];
    const float* loraB  = (const float*)d_in[5];
    float* out = (float*)d_out;

    prep_kernel<<<MTOT, 256>>>(x, loraA);

    static int smem_set = 0;
    if (!smem_set) {
        cudaFuncSetAttribute(qmain_kernel,
                             cudaFuncAttributeMaxDynamicSharedMemorySize,
                             SMEM_BYTES);
        smem_set = 1;
    }
    dim3 grid(OUTD / NTILE, KSPLIT);
    qmain_kernel<<<grid, 256, SMEM_BYTES>>>(W, zeros, scales);

    dim3 rgrid((OUTD / 4 + 255) / 256, MTOT);
    reduce_kernel<<<rgrid, 256>>>(loraB, out);
}

// round 6
// speedup vs baseline: 3.9497x; 1.3446x over previous
#include <cuda_runtime.h>
#include <cuda_bf16.h>
#include <stdint.h>

// QLoRALinear: out[128,11008] = x @ dequant_int4(W) + 2*(x@A^T)@B^T
// Round 6: factored-scale 2-term bf16 mma.sync:
//   out = sum_g s[g,o] * ( (x_hi + x_lo) @ (q - z)_g )   with (q-z) EXACT in bf16.
// ldmatrix fragment loads, group-wise scale fold in fp32, KSPLIT=4.

#define OUTD 11008
#define IND  4096
#define MTOT 128
#define RLORA 16

#define NTILE 64                    // o per block
#define KSPLIT 4
#define KC 64                       // k per chunk
#define NCH (IND / KSPLIT / KC)     // 16 chunks per block
#define NGRP (NCH / 2)              // 8 groups per block (group = 128 k)
#define NCHUNK_TOT (IND / KC)       // 64 tiles in prep layout
#define ROWH 72                     // halves per tile row (64 data + 8 pad)

// per-buffer smem offsets (halves)
#define XH_OFF 0
#define XL_OFF 9216                 // 128*72
#define WQ_OFF 18432                // + 128*72
#define BUF_H  23040                // + 64*72
#define SMEM_BYTES (2 * BUF_H * 2)  // 92160 B dynamic

// ---- device scratch ----
__device__ __align__(16) uint16_t g_xh[NCHUNK_TOT * MTOT * ROWH];
__device__ __align__(16) uint16_t g_xl[NCHUNK_TOT * MTOT * ROWH];
__device__ __align__(16) float    g_xa[MTOT * RLORA];         // 2 * x @ A^T
__device__ float g_partial[KSPLIT * MTOT * OUTD];             // 22.5 MB

// ---------------------------------------------------------------------------
__device__ __forceinline__ uint32_t pack_bf16x2(float lo, float hi) {
    uint32_t r;
    asm("cvt.rn.bf16x2.f32 %0, %1, %2;" : "=r"(r) : "f"(hi), "f"(lo));
    return r;
}
__device__ __forceinline__ uint32_t smem_u32(const void* p) {
    uint32_t a;
    asm("{ .reg .u64 t; cvta.to.shared.u64 t, %1; cvt.u32.u64 %0, t; }"
        : "=r"(a) : "l"(p));
    return a;
}
__device__ __forceinline__ void cp16(uint32_t dst, const void* src) {
    asm volatile("cp.async.cg.shared.global [%0], [%1], 16;"
                 :: "r"(dst), "l"(src) : "memory");
}
__device__ __forceinline__ void mma16816(float* d, const uint32_t* a,
                                         uint32_t b0, uint32_t b1) {
    asm volatile(
        "mma.sync.aligned.m16n8k16.row.col.f32.bf16.bf16.f32 "
        "{%0,%1,%2,%3}, {%4,%5,%6,%7}, {%8,%9}, {%0,%1,%2,%3};"
        : "+f"(d[0]), "+f"(d[1]), "+f"(d[2]), "+f"(d[3])
        : "r"(a[0]), "r"(a[1]), "r"(a[2]), "r"(a[3]), "r"(b0), "r"(b1));
}
__device__ __forceinline__ void ldm4(uint32_t* r, uint32_t addr) {
    asm volatile("ldmatrix.sync.aligned.m8n8.x4.shared.b16 {%0,%1,%2,%3}, [%4];"
                 : "=r"(r[0]), "=r"(r[1]), "=r"(r[2]), "=r"(r[3]) : "r"(addr));
}

// ---------------------------------------------------------------------------
// Prep: split x into bf16 hi/lo tile images + xa = 2*(x @ A^T)
// ---------------------------------------------------------------------------
__global__ __launch_bounds__(256) void prep_kernel(const float* __restrict__ x,
                                                   const float* __restrict__ A) {
    const int m = blockIdx.x;
    const int t = threadIdx.x;
    const int wid = t >> 5, lane = t & 31;
    const int k0 = t * 16;

    float xv[16];
#pragma unroll
    for (int q = 0; q < 4; q++)
        *(float4*)&xv[4 * q] = *(const float4*)(x + (size_t)m * IND + k0 + 4 * q);

    uint32_t hw[8], lw[8];
#pragma unroll
    for (int p = 0; p < 8; p++) {
        const float f0 = xv[2 * p], f1 = xv[2 * p + 1];
        const uint32_t h2 = pack_bf16x2(f0, f1);
        const float b0 = __uint_as_float(h2 << 16);
        const float b1 = __uint_as_float(h2 & 0xffff0000u);
        hw[p] = h2;
        lw[p] = pack_bf16x2(f0 - b0, f1 - b1);
    }
    const int chunk = t >> 2;
    const size_t base = ((size_t)chunk * MTOT + m) * ROWH + (t & 3) * 16;
    uint4* ph = (uint4*)(g_xh + base);
    uint4* pl = (uint4*)(g_xl + base);
    ph[0] = make_uint4(hw[0], hw[1], hw[2], hw[3]);
    ph[1] = make_uint4(hw[4], hw[5], hw[6], hw[7]);
    pl[0] = make_uint4(lw[0], lw[1], lw[2], lw[3]);
    pl[1] = make_uint4(lw[4], lw[5], lw[6], lw[7]);

    float acc[RLORA];
#pragma unroll
    for (int r = 0; r < RLORA; r++) acc[r] = 0.0f;
#pragma unroll
    for (int r = 0; r < RLORA; r++) {
        const float* Ar = A + (size_t)r * IND + k0;
#pragma unroll
        for (int q = 0; q < 4; q++) {
            const float4 a4 = *(const float4*)(Ar + 4 * q);
            acc[r] = fmaf(xv[4 * q + 0], a4.x, acc[r]);
            acc[r] = fmaf(xv[4 * q + 1], a4.y, acc[r]);
            acc[r] = fmaf(xv[4 * q + 2], a4.z, acc[r]);
            acc[r] = fmaf(xv[4 * q + 3], a4.w, acc[r]);
        }
    }
#pragma unroll
    for (int r = 0; r < RLORA; r++)
#pragma unroll
        for (int off = 16; off > 0; off >>= 1)
            acc[r] += __shfl_xor_sync(0xffffffffu, acc[r], off);

    __shared__ float red[8][RLORA];
    if (lane == 0)
#pragma unroll
        for (int r = 0; r < RLORA; r++) red[wid][r] = acc[r];
    __syncthreads();
    if (t < RLORA) {
        float s = 0.0f;
#pragma unroll
        for (int w = 0; w < 8; w++) s += red[w][t];
        g_xa[m * RLORA + t] = 2.0f * s;
    }
}

// ---------------------------------------------------------------------------
// Main GEMM: grid (172, 4), 256 threads (8 warps; warp tile 32m x 32o)
// ---------------------------------------------------------------------------
__global__ __launch_bounds__(256, 2) void qmain_kernel(
    const int*   __restrict__ W,
    const int*   __restrict__ zeros,
    const float* __restrict__ scales)
{
    extern __shared__ __align__(16) uint16_t sm[];
    __shared__ float sS[NGRP][NTILE];   // scales, this block's groups
    __shared__ int   zS[NGRP][NTILE];   // zero points
    const uint32_t smb = smem_u32(sm);

    const int t = threadIdx.x;
    const int lane = t & 31;
    const int wid = t >> 5;
    const int wm = wid & 3;             // 32-row m group
    const int wo = wid >> 2;            // 32-col o group
    const int obase = blockIdx.x * NTILE;
    const int kq4 = blockIdx.y;         // k quarter
    const int gbase = kq4 * NGRP;

    // staging mapping
    const int so  = t & 63;
    const int skq = t >> 6;
    const int xrow = t >> 1;
    const int xhalf = t & 1;

    // stage scales / zeros for this block
    for (int idx = t; idx < NGRP * NTILE; idx += 256) {
        const int g = idx >> 6, o = idx & 63;
        sS[g][o] = scales[(size_t)(gbase + g) * OUTD + obase + o];
        zS[g][o] = zeros[(size_t)(gbase + g) * OUTD + obase + o];
    }

    // ldmatrix lane address components
    const int rowA = (lane & 7) + ((lane >> 3) & 1) * 8;
    const int kA   = ((lane >> 4) & 1) * 8;
    const int rowB = (lane & 7) + ((lane >> 4) & 1) * 8;
    const int kB   = ((lane >> 3) & 1) * 8;

    float facc[2][4][4];                 // final fp32
    float gacc[2][4][4];                 // per-group MMA accum
#pragma unroll
    for (int mt = 0; mt < 2; mt++)
#pragma unroll
        for (int ot = 0; ot < 4; ot++)
#pragma unroll
            for (int i = 0; i < 4; i++) { facc[mt][ot][i] = 0.f; gacc[mt][ot][i] = 0.f; }

    int buf = 0;

    auto stage = [&](int b, int c) {
        const int ck = kq4 * NCH + c;
        // x hi/lo via cp.async
        {
            const size_t src = ((size_t)ck * MTOT + xrow) * ROWH + xhalf * 32;
            const uint32_t dxh = smb + (b * BUF_H + XH_OFF + xrow * ROWH + xhalf * 32) * 2;
            const uint32_t dxl = smb + (b * BUF_H + XL_OFF + xrow * ROWH + xhalf * 32) * 2;
#pragma unroll
            for (int j = 0; j < 4; j++) {
                cp16(dxh + j * 16, g_xh + src + j * 8);
                cp16(dxl + j * 16, g_xl + src + j * 8);
            }
            asm volatile("cp.async.commit_group;" ::: "memory");
        }
        // W: q - z exact in bf16
        {
            const int g = c >> 1;
            const int z = zS[g][so];
            const int k0 = (ck) * KC;
            const int* Wp = W + (size_t)(k0 + skq * 16) * OUTD + obase + so;
            uint32_t hp[8];
#pragma unroll
            for (int p = 0; p < 8; p++) {
                const int q0 = Wp[(size_t)(2 * p) * OUTD];
                const int q1 = Wp[(size_t)(2 * p + 1) * OUTD];
                hp[p] = pack_bf16x2((float)(q0 - z), (float)(q1 - z));
            }
            uint16_t* wq = sm + b * BUF_H + WQ_OFF + so * ROWH + skq * 16;
            ((uint4*)wq)[0] = make_uint4(hp[0], hp[1], hp[2], hp[3]);
            ((uint4*)wq)[1] = make_uint4(hp[4], hp[5], hp[6], hp[7]);
        }
    };

    stage(0, 0);
    asm volatile("cp.async.wait_group 0;" ::: "memory");
    __syncthreads();

    const int arow = lane >> 2;
    const int acol = (lane & 3) * 2;

    // per-buffer ldmatrix base addrs (halves scaled to bytes later)
    const int aoffH0 = XH_OFF + (wm * 32 + 0 * 16 + rowA) * ROWH + kA;
    const int aoffH1 = XH_OFF + (wm * 32 + 1 * 16 + rowA) * ROWH + kA;
    const int aoffL0 = XL_OFF + (wm * 32 + 0 * 16 + rowA) * ROWH + kA;
    const int aoffL1 = XL_OFF + (wm * 32 + 1 * 16 + rowA) * ROWH + kA;
    const int boff0  = WQ_OFF + (wo * 32 + 0 * 16 + rowB) * ROWH + kB;
    const int boff1  = WQ_OFF + (wo * 32 + 1 * 16 + rowB) * ROWH + kB;

#pragma unroll 1
    for (int c = 0; c < NCH; c++) {
        if (c + 1 < NCH) stage(buf ^ 1, c + 1);

        const uint32_t bb = smb + (buf * BUF_H) * 2;

#pragma unroll
        for (int ks = 0; ks < KC; ks += 16) {
            uint32_t ah0[4], ah1[4], al0[4], al1[4], bq0[4], bq1[4];
            ldm4(ah0, bb + (aoffH0 + ks) * 2);
            ldm4(ah1, bb + (aoffH1 + ks) * 2);
            ldm4(al0, bb + (aoffL0 + ks) * 2);
            ldm4(al1, bb + (aoffL1 + ks) * 2);
            ldm4(bq0, bb + (boff0 + ks) * 2);
            ldm4(bq1, bb + (boff1 + ks) * 2);

#pragma unroll
            for (int ot = 0; ot < 4; ot++) {
                const uint32_t b0 = (ot < 2) ? bq0[2 * ot]     : bq1[2 * (ot - 2)];
                const uint32_t b1 = (ot < 2) ? bq0[2 * ot + 1] : bq1[2 * (ot - 2) + 1];
                mma16816(gacc[0][ot], ah0, b0, b1);
                mma16816(gacc[0][ot], al0, b0, b1);
                mma16816(gacc[1][ot], ah1, b0, b1);
                mma16816(gacc[1][ot], al1, b0, b1);
            }
        }

        // group fold every 2 chunks (group = 128 k)
        if (c & 1) {
            const int g = c >> 1;
#pragma unroll
            for (int ot = 0; ot < 4; ot++) {
                const float2 sv = *(const float2*)&sS[g][wo * 32 + ot * 8 + acol];
#pragma unroll
                for (int mt = 0; mt < 2; mt++) {
                    facc[mt][ot][0] = fmaf(sv.x, gacc[mt][ot][0], facc[mt][ot][0]);
                    facc[mt][ot][1] = fmaf(sv.y, gacc[mt][ot][1], facc[mt][ot][1]);
                    facc[mt][ot][2] = fmaf(sv.x, gacc[mt][ot][2], facc[mt][ot][2]);
                    facc[mt][ot][3] = fmaf(sv.y, gacc[mt][ot][3], facc[mt][ot][3]);
                    gacc[mt][ot][0] = 0.f; gacc[mt][ot][1] = 0.f;
                    gacc[mt][ot][2] = 0.f; gacc[mt][ot][3] = 0.f;
                }
            }
        }

        asm volatile("cp.async.wait_group 0;" ::: "memory");
        __syncthreads();
        buf ^= 1;
    }

    // ---- store partials ----
    float* pp = g_partial + (size_t)kq4 * MTOT * OUTD;
#pragma unroll
    for (int mt = 0; mt < 2; mt++) {
        const int r0 = wm * 32 + mt * 16 + arow;
#pragma unroll
        for (int ot = 0; ot < 4; ot++) {
            const int cabs = obase + wo * 32 + ot * 8 + acol;
            *(float2*)&pp[(size_t)r0 * OUTD + cabs] =
                make_float2(facc[mt][ot][0], facc[mt][ot][1]);
            *(float2*)&pp[(size_t)(r0 + 8) * OUTD + cabs] =
                make_float2(facc[mt][ot][2], facc[mt][ot][3]);
        }
    }
}

// ---------------------------------------------------------------------------
// Reduce partials + LoRA epilogue.
// ---------------------------------------------------------------------------
__global__ __launch_bounds__(256) void reduce_kernel(
    const float* __restrict__ loraB,
    float*       __restrict__ out)
{
    const int m = blockIdx.y;
    const int oc = blockIdx.x * 256 + threadIdx.x;

    __shared__ float sxa[RLORA];
    if (threadIdx.x < RLORA) sxa[threadIdx.x] = g_xa[m * RLORA + threadIdx.x];
    __syncthreads();

    if (oc >= OUTD / 4) return;
    const int o = 4 * oc;

    float4 s = make_float4(0.f, 0.f, 0.f, 0.f);
#pragma unroll
    for (int p = 0; p < KSPLIT; p++) {
        const float4 v = *(const float4*)&g_partial[(size_t)p * MTOT * OUTD +
                                                    (size_t)m * OUTD + o];
        s.x += v.x; s.y += v.y; s.z += v.z; s.w += v.w;
    }
    float l[4] = {0.f, 0.f, 0.f, 0.f};
#pragma unroll
    for (int j = 0; j < 4; j++) {
        const float* Bp = loraB + (size_t)(o + j) * RLORA;
#pragma unroll
        for (int r = 0; r < RLORA; r++)
            l[j] = fmaf(sxa[r], Bp[r], l[j]);
    }
    s.x += l[0]; s.y += l[1]; s.z += l[2]; s.w += l[3];
    *(float4*)&out[(size_t)m * OUTD + o] = s;
}

// ---------------------------------------------------------------------------
extern "C" void kernel_launch(void* const* d_in, const int* in_sizes, int n_in,
                              void* d_out, int out_size) {
    const float* x      = (const float*)d_in[0];
    const int*   W      = (const int*)  d_in[1];
    const int*   zeros  = (const int*)  d_in[2];
    const float* scales = (const float*)d_in[3];
    const float* loraA  = (const float*)d_in[4];
    const float* loraB  = (const float*)d_in[5];
    float* out = (float*)d_out;

    cudaFuncSetAttribute(qmain_kernel,
                         cudaFuncAttributeMaxDynamicSharedMemorySize, SMEM_BYTES);

    prep_kernel<<<MTOT, 256>>>(x, loraA);

    dim3 grid(OUTD / NTILE, KSPLIT);
    qmain_kernel<<<grid, 256, SMEM_BYTES>>>(W, zeros, scales);

    dim3 rgrid((OUTD / 4 + 255) / 256, MTOT);
    reduce_kernel<<<rgrid, 256>>>(loraB, out);
}

// round 7
// speedup vs baseline: 4.8549x; 1.2292x over previous
#include <cuda_runtime.h>
#include <cuda_fp16.h>
#include <stdint.h>

// QLoRALinear: out[128,11008] = x @ dequant_int4(W) + 2*(x@A^T)@B^T
// Round 7: single-term fp16 mma.sync with factored scales:
//   out = sum_g s[g,o] * ( x_f16 @ (q - z)_g )   ; (q-z) EXACT in fp16.
// KSPLIT=8, parallel prep with atomic xa reduction.

#define OUTD 11008
#define IND  4096
#define MTOT 128
#define RLORA 16

#define NTILE 64                    // o per block
#define KSPLIT 8
#define KC 64                       // k per chunk
#define NCH (IND / KSPLIT / KC)     // 8 chunks per block
#define NGRP (NCH / 2)              // 4 groups per block (group = 128 k)
#define NCHUNK_TOT (IND / KC)       // 64 tiles in prep layout
#define ROWH 72                     // halves per tile row (64 data + 8 pad)

// per-buffer smem offsets (halves)
#define XH_OFF 0
#define WQ_OFF 9216                 // 128*72
#define BUF_H  13824                // + 64*72
#define SMEM_BYTES (2 * BUF_H * 2)  // 55296 B dynamic

// ---- device scratch ----
__device__ __align__(16) uint16_t g_xh[NCHUNK_TOT * MTOT * ROWH];  // fp16 x tiles
__device__ __align__(16) float    g_xa[MTOT * RLORA];              // 2 * x @ A^T
__device__ float g_partial[KSPLIT * MTOT * OUTD];                  // 45 MB

// ---------------------------------------------------------------------------
__device__ __forceinline__ uint32_t pack_f16x2(float lo, float hi) {
    uint32_t r;
    asm("cvt.rn.f16x2.f32 %0, %1, %2;" : "=r"(r) : "f"(hi), "f"(lo));
    return r;
}
__device__ __forceinline__ uint32_t smem_u32(const void* p) {
    uint32_t a;
    asm("{ .reg .u64 t; cvta.to.shared.u64 t, %1; cvt.u32.u64 %0, t; }"
        : "=r"(a) : "l"(p));
    return a;
}
__device__ __forceinline__ void cp16(uint32_t dst, const void* src) {
    asm volatile("cp.async.cg.shared.global [%0], [%1], 16;"
                 :: "r"(dst), "l"(src) : "memory");
}
__device__ __forceinline__ void mma16816(float* d, const uint32_t* a,
                                         uint32_t b0, uint32_t b1) {
    asm volatile(
        "mma.sync.aligned.m16n8k16.row.col.f32.f16.f16.f32 "
        "{%0,%1,%2,%3}, {%4,%5,%6,%7}, {%8,%9}, {%0,%1,%2,%3};"
        : "+f"(d[0]), "+f"(d[1]), "+f"(d[2]), "+f"(d[3])
        : "r"(a[0]), "r"(a[1]), "r"(a[2]), "r"(a[3]), "r"(b0), "r"(b1));
}
__device__ __forceinline__ void ldm4(uint32_t* r, uint32_t addr) {
    asm volatile("ldmatrix.sync.aligned.m8n8.x4.shared.b16 {%0,%1,%2,%3}, [%4];"
                 : "=r"(r[0]), "=r"(r[1]), "=r"(r[2]), "=r"(r[3]) : "r"(addr));
}

// ---------------------------------------------------------------------------
// zero xa
// ---------------------------------------------------------------------------
__global__ void zero_xa_kernel() {
    g_xa[threadIdx.x + blockIdx.x * 1024] = 0.0f;
}

// ---------------------------------------------------------------------------
// Prep: x -> fp16 tile image + xa partial (atomic).
// grid (128 m, 4 kq), 256 threads; each thread handles 4 consecutive k.
// ---------------------------------------------------------------------------
__global__ __launch_bounds__(256) void prep_kernel(const float* __restrict__ x,
                                                   const float* __restrict__ A) {
    const int m  = blockIdx.x;
    const int kq = blockIdx.y;
    const int t  = threadIdx.x;
    const int wid = t >> 5, lane = t & 31;
    const int k0 = kq * 1024 + t * 4;

    const float4 xv = *(const float4*)(x + (size_t)m * IND + k0);

    // fp16 convert + store into tile image
    const int chunk = k0 >> 6;
    const int koff  = k0 & 63;
    uint2 hp;
    hp.x = pack_f16x2(xv.x, xv.y);
    hp.y = pack_f16x2(xv.z, xv.w);
    *(uint2*)(g_xh + ((size_t)chunk * MTOT + m) * ROWH + koff) = hp;

    // xa partials
    float acc[RLORA];
#pragma unroll
    for (int r = 0; r < RLORA; r++) {
        const float4 a4 = *(const float4*)(A + (size_t)r * IND + k0);
        float s = xv.x * a4.x;
        s = fmaf(xv.y, a4.y, s);
        s = fmaf(xv.z, a4.z, s);
        s = fmaf(xv.w, a4.w, s);
        acc[r] = s;
    }
#pragma unroll
    for (int r = 0; r < RLORA; r++)
#pragma unroll
        for (int off = 16; off > 0; off >>= 1)
            acc[r] += __shfl_xor_sync(0xffffffffu, acc[r], off);

    __shared__ float red[8][RLORA];
    if (lane == 0)
#pragma unroll
        for (int r = 0; r < RLORA; r++) red[wid][r] = acc[r];
    __syncthreads();
    if (t < RLORA) {
        float s = 0.0f;
#pragma unroll
        for (int w = 0; w < 8; w++) s += red[w][t];
        atomicAdd(&g_xa[m * RLORA + t], 2.0f * s);
    }
}

// ---------------------------------------------------------------------------
// Main GEMM: grid (172, 8), 256 threads (8 warps; warp tile 32m x 32o)
// ---------------------------------------------------------------------------
__global__ __launch_bounds__(256, 2) void qmain_kernel(
    const int*   __restrict__ W,
    const int*   __restrict__ zeros,
    const float* __restrict__ scales)
{
    extern __shared__ __align__(16) uint16_t sm[];
    __shared__ float sS[NGRP][NTILE];
    __shared__ int   zS[NGRP][NTILE];
    const uint32_t smb = smem_u32(sm);

    const int t = threadIdx.x;
    const int lane = t & 31;
    const int wid = t >> 5;
    const int wm = wid & 3;
    const int wo = wid >> 2;
    const int obase = blockIdx.x * NTILE;
    const int kq8 = blockIdx.y;
    const int gbase = kq8 * NGRP;

    const int so  = t & 63;
    const int skq = t >> 6;
    const int xrow = t >> 1;
    const int xhalf = t & 1;

    // stage scales / zeros (exactly 256 entries)
    {
        const int g = t >> 6, o = t & 63;
        sS[g][o] = scales[(size_t)(gbase + g) * OUTD + obase + o];
        zS[g][o] = zeros[(size_t)(gbase + g) * OUTD + obase + o];
    }

    const int rowA = (lane & 7) + ((lane >> 3) & 1) * 8;
    const int kA   = ((lane >> 4) & 1) * 8;
    const int rowB = (lane & 7) + ((lane >> 4) & 1) * 8;
    const int kB   = ((lane >> 3) & 1) * 8;

    float facc[2][4][4];
    float gacc[2][4][4];
#pragma unroll
    for (int mt = 0; mt < 2; mt++)
#pragma unroll
        for (int ot = 0; ot < 4; ot++)
#pragma unroll
            for (int i = 0; i < 4; i++) { facc[mt][ot][i] = 0.f; gacc[mt][ot][i] = 0.f; }

    int buf = 0;

    auto stage = [&](int b, int c) {
        const int ck = kq8 * NCH + c;
        // x fp16 tile via cp.async
        {
            const size_t src = ((size_t)ck * MTOT + xrow) * ROWH + xhalf * 32;
            const uint32_t dxh = smb + (b * BUF_H + XH_OFF + xrow * ROWH + xhalf * 32) * 2;
#pragma unroll
            for (int j = 0; j < 4; j++)
                cp16(dxh + j * 16, g_xh + src + j * 8);
            asm volatile("cp.async.commit_group;" ::: "memory");
        }
        // W: (q - z) exact in fp16
        {
            const int g = c >> 1;
            const int z = zS[g][so];
            const int k0 = ck * KC;
            const int* Wp = W + (size_t)(k0 + skq * 16) * OUTD + obase + so;
            uint32_t hp[8];
#pragma unroll
            for (int p = 0; p < 8; p++) {
                const int q0 = Wp[(size_t)(2 * p) * OUTD];
                const int q1 = Wp[(size_t)(2 * p + 1) * OUTD];
                hp[p] = pack_f16x2((float)(q0 - z), (float)(q1 - z));
            }
            uint16_t* wq = sm + b * BUF_H + WQ_OFF + so * ROWH + skq * 16;
            ((uint4*)wq)[0] = make_uint4(hp[0], hp[1], hp[2], hp[3]);
            ((uint4*)wq)[1] = make_uint4(hp[4], hp[5], hp[6], hp[7]);
        }
    };

    __syncthreads();   // sS/zS ready (stage reads zS)
    stage(0, 0);
    asm volatile("cp.async.wait_group 0;" ::: "memory");
    __syncthreads();

    const int arow = lane >> 2;
    const int acol = (lane & 3) * 2;

    const int aoff0 = XH_OFF + (wm * 32 + 0 * 16 + rowA) * ROWH + kA;
    const int aoff1 = XH_OFF + (wm * 32 + 1 * 16 + rowA) * ROWH + kA;
    const int boff0 = WQ_OFF + (wo * 32 + 0 * 16 + rowB) * ROWH + kB;
    const int boff1 = WQ_OFF + (wo * 32 + 1 * 16 + rowB) * ROWH + kB;

#pragma unroll 1
    for (int c = 0; c < NCH; c++) {
        if (c + 1 < NCH) stage(buf ^ 1, c + 1);

        const uint32_t bb = smb + (buf * BUF_H) * 2;

#pragma unroll
        for (int ks = 0; ks < KC; ks += 16) {
            uint32_t a0[4], a1[4], bq0[4], bq1[4];
            ldm4(a0, bb + (aoff0 + ks) * 2);
            ldm4(a1, bb + (aoff1 + ks) * 2);
            ldm4(bq0, bb + (boff0 + ks) * 2);
            ldm4(bq1, bb + (boff1 + ks) * 2);

#pragma unroll
            for (int ot = 0; ot < 4; ot++) {
                const uint32_t b0 = (ot < 2) ? bq0[2 * ot]     : bq1[2 * (ot - 2)];
                const uint32_t b1 = (ot < 2) ? bq0[2 * ot + 1] : bq1[2 * (ot - 2) + 1];
                mma16816(gacc[0][ot], a0, b0, b1);
                mma16816(gacc[1][ot], a1, b0, b1);
            }
        }

        // fold group scale every 2 chunks (group = 128 k)
        if (c & 1) {
            const int g = c >> 1;
#pragma unroll
            for (int ot = 0; ot < 4; ot++) {
                const float2 sv = *(const float2*)&sS[g][wo * 32 + ot * 8 + acol];
#pragma unroll
                for (int mt = 0; mt < 2; mt++) {
                    facc[mt][ot][0] = fmaf(sv.x, gacc[mt][ot][0], facc[mt][ot][0]);
                    facc[mt][ot][1] = fmaf(sv.y, gacc[mt][ot][1], facc[mt][ot][1]);
                    facc[mt][ot][2] = fmaf(sv.x, gacc[mt][ot][2], facc[mt][ot][2]);
                    facc[mt][ot][3] = fmaf(sv.y, gacc[mt][ot][3], facc[mt][ot][3]);
                    gacc[mt][ot][0] = 0.f; gacc[mt][ot][1] = 0.f;
                    gacc[mt][ot][2] = 0.f; gacc[mt][ot][3] = 0.f;
                }
            }
        }

        asm volatile("cp.async.wait_group 0;" ::: "memory");
        __syncthreads();
        buf ^= 1;
    }

    // ---- store partials ----
    float* pp = g_partial + (size_t)kq8 * MTOT * OUTD;
#pragma unroll
    for (int mt = 0; mt < 2; mt++) {
        const int r0 = wm * 32 + mt * 16 + arow;
#pragma unroll
        for (int ot = 0; ot < 4; ot++) {
            const int cabs = obase + wo * 32 + ot * 8 + acol;
            *(float2*)&pp[(size_t)r0 * OUTD + cabs] =
                make_float2(facc[mt][ot][0], facc[mt][ot][1]);
            *(float2*)&pp[(size_t)(r0 + 8) * OUTD + cabs] =
                make_float2(facc[mt][ot][2], facc[mt][ot][3]);
        }
    }
}

// ---------------------------------------------------------------------------
// Reduce partials + LoRA epilogue.
// ---------------------------------------------------------------------------
__global__ __launch_bounds__(256) void reduce_kernel(
    const float* __restrict__ loraB,
    float*       __restrict__ out)
{
    const int m = blockIdx.y;
    const int oc = blockIdx.x * 256 + threadIdx.x;

    __shared__ float sxa[RLORA];
    if (threadIdx.x < RLORA) sxa[threadIdx.x] = g_xa[m * RLORA + threadIdx.x];
    __syncthreads();

    if (oc >= OUTD / 4) return;
    const int o = 4 * oc;

    float4 s = make_float4(0.f, 0.f, 0.f, 0.f);
#pragma unroll
    for (int p = 0; p < KSPLIT; p++) {
        const float4 v = *(const float4*)&g_partial[(size_t)p * MTOT * OUTD +
                                                    (size_t)m * OUTD + o];
        s.x += v.x; s.y += v.y; s.z += v.z; s.w += v.w;
    }
    float l[4] = {0.f, 0.f, 0.f, 0.f};
#pragma unroll
    for (int j = 0; j < 4; j++) {
        const float* Bp = loraB + (size_t)(o + j) * RLORA;
#pragma unroll
        for (int r = 0; r < RLORA; r++)
            l[j] = fmaf(sxa[r], Bp[r], l[j]);
    }
    s.x += l[0]; s.y += l[1]; s.z += l[2]; s.w += l[3];
    *(float4*)&out[(size_t)m * OUTD + o] = s;
}

// ---------------------------------------------------------------------------
extern "C" void kernel_launch(void* const* d_in, const int* in_sizes, int n_in,
                              void* d_out, int out_size) {
    const float* x      = (const float*)d_in[0];
    const int*   W      = (const int*)  d_in[1];
    const int*   zeros  = (const int*)  d_in[2];
    const float* scales = (const float*)d_in[3];
    const float* loraA  = (const float*)d_in[4];
    const float* loraB  = (const float*)d_in[5];
    float* out = (float*)d_out;

    cudaFuncSetAttribute(qmain_kernel,
                         cudaFuncAttributeMaxDynamicSharedMemorySize, SMEM_BYTES);

    zero_xa_kernel<<<2, 1024>>>();

    dim3 pgrid(MTOT, 4);
    prep_kernel<<<pgrid, 256>>>(x, loraA);

    dim3 grid(OUTD / NTILE, KSPLIT);
    qmain_kernel<<<grid, 256, SMEM_BYTES>>>(W, zeros, scales);

    dim3 rgrid((OUTD / 4 + 255) / 256, MTOT);
    reduce_kernel<<<rgrid, 256>>>(loraB, out);
}

// round 8
// speedup vs baseline: 8.5952x; 1.7704x over previous
#include <cuda_runtime.h>
#include <cuda_fp16.h>
#include <stdint.h>

// QLoRALinear: out[128,11008] = x @ dequant_int4(W) + 2*(x@A^T)@B^T
// Round 8: fp16 single-term mma (factored scales, (q-z) exact), KSPLIT=4,
// LoRA folded into main kernel epilogue (kq==0 blocks), W LDG software-pipelined,
// reduce kernel reduced to a pure partial sum.

#define OUTD 11008
#define IND  4096
#define MTOT 128
#define RLORA 16

#define NTILE 64                    // o per block
#define KSPLIT 4
#define KC 64                       // k per chunk
#define NCH (IND / KSPLIT / KC)     // 16 chunks per block
#define NGRP (NCH / 2)              // 8 groups per block (group = 128 k)
#define NCHUNK_TOT (IND / KC)       // 64 tiles in prep layout
#define ROWH 72                     // halves per tile row (64 data + 8 pad)

// per-buffer smem offsets (halves)
#define XH_OFF 0
#define WQ_OFF 9216                 // 128*72
#define BUF_H  13824                // + 64*72
#define SMEM_BYTES (2 * BUF_H * 2)  // 55296 B dynamic

// ---- device scratch ----
__device__ __align__(16) uint16_t g_xh[NCHUNK_TOT * MTOT * ROWH];  // fp16 x tiles
__device__ __align__(16) float    g_xa[MTOT * RLORA];              // 2 * x @ A^T
__device__ float g_partial[KSPLIT * MTOT * OUTD];                  // 22.5 MB

// ---------------------------------------------------------------------------
__device__ __forceinline__ uint32_t pack_f16x2(float lo, float hi) {
    uint32_t r;
    asm("cvt.rn.f16x2.f32 %0, %1, %2;" : "=r"(r) : "f"(hi), "f"(lo));
    return r;
}
__device__ __forceinline__ uint32_t smem_u32(const void* p) {
    uint32_t a;
    asm("{ .reg .u64 t; cvta.to.shared.u64 t, %1; cvt.u32.u64 %0, t; }"
        : "=r"(a) : "l"(p));
    return a;
}
__device__ __forceinline__ void cp16(uint32_t dst, const void* src) {
    asm volatile("cp.async.cg.shared.global [%0], [%1], 16;"
                 :: "r"(dst), "l"(src) : "memory");
}
__device__ __forceinline__ void mma16816(float* d, const uint32_t* a,
                                         uint32_t b0, uint32_t b1) {
    asm volatile(
        "mma.sync.aligned.m16n8k16.row.col.f32.f16.f16.f32 "
        "{%0,%1,%2,%3}, {%4,%5,%6,%7}, {%8,%9}, {%0,%1,%2,%3};"
        : "+f"(d[0]), "+f"(d[1]), "+f"(d[2]), "+f"(d[3])
        : "r"(a[0]), "r"(a[1]), "r"(a[2]), "r"(a[3]), "r"(b0), "r"(b1));
}
__device__ __forceinline__ void ldm4(uint32_t* r, uint32_t addr) {
    asm volatile("ldmatrix.sync.aligned.m8n8.x4.shared.b16 {%0,%1,%2,%3}, [%4];"
                 : "=r"(r[0]), "=r"(r[1]), "=r"(r[2]), "=r"(r[3]) : "r"(addr));
}

// ---------------------------------------------------------------------------
__global__ void zero_xa_kernel() {
    g_xa[threadIdx.x + blockIdx.x * 1024] = 0.0f;
}

// ---------------------------------------------------------------------------
// Prep: x -> fp16 tile image + xa partial (atomic). grid (128, 4), 256 thr.
// ---------------------------------------------------------------------------
__global__ __launch_bounds__(256) void prep_kernel(const float* __restrict__ x,
                                                   const float* __restrict__ A) {
    const int m  = blockIdx.x;
    const int kq = blockIdx.y;
    const int t  = threadIdx.x;
    const int wid = t >> 5, lane = t & 31;
    const int k0 = kq * 1024 + t * 4;

    const float4 xv = *(const float4*)(x + (size_t)m * IND + k0);

    const int chunk = k0 >> 6;
    const int koff  = k0 & 63;
    uint2 hp;
    hp.x = pack_f16x2(xv.x, xv.y);
    hp.y = pack_f16x2(xv.z, xv.w);
    *(uint2*)(g_xh + ((size_t)chunk * MTOT + m) * ROWH + koff) = hp;

    float acc[RLORA];
#pragma unroll
    for (int r = 0; r < RLORA; r++) {
        const float4 a4 = *(const float4*)(A + (size_t)r * IND + k0);
        float s = xv.x * a4.x;
        s = fmaf(xv.y, a4.y, s);
        s = fmaf(xv.z, a4.z, s);
        s = fmaf(xv.w, a4.w, s);
        acc[r] = s;
    }
#pragma unroll
    for (int r = 0; r < RLORA; r++)
#pragma unroll
        for (int off = 16; off > 0; off >>= 1)
            acc[r] += __shfl_xor_sync(0xffffffffu, acc[r], off);

    __shared__ float red[8][RLORA];
    if (lane == 0)
#pragma unroll
        for (int r = 0; r < RLORA; r++) red[wid][r] = acc[r];
    __syncthreads();
    if (t < RLORA) {
        float s = 0.0f;
#pragma unroll
        for (int w = 0; w < 8; w++) s += red[w][t];
        atomicAdd(&g_xa[m * RLORA + t], 2.0f * s);
    }
}

// ---------------------------------------------------------------------------
// Main GEMM: grid (172, 4), 256 threads (8 warps; warp tile 32m x 32o)
// ---------------------------------------------------------------------------
__global__ __launch_bounds__(256, 2) void qmain_kernel(
    const int*   __restrict__ W,
    const int*   __restrict__ zeros,
    const float* __restrict__ scales,
    const float* __restrict__ loraB)
{
    extern __shared__ __align__(16) uint16_t sm[];
    __shared__ float sS[NGRP][NTILE];
    __shared__ int   zS[NGRP][NTILE];
    __shared__ __align__(16) float sB[NTILE][RLORA];   // loraB tile
    __shared__ __align__(16) float sxa[MTOT][RLORA];   // 2 * x @ A^T
    const uint32_t smb = smem_u32(sm);

    const int t = threadIdx.x;
    const int lane = t & 31;
    const int wid = t >> 5;
    const int wm = wid & 3;
    const int wo = wid >> 2;
    const int obase = blockIdx.x * NTILE;
    const int kq4 = blockIdx.y;
    const int gbase = kq4 * NGRP;

    const int so  = t & 63;
    const int skq = t >> 6;
    const int xrow = t >> 1;
    const int xhalf = t & 1;

    // stage scales / zeros (512 entries)
#pragma unroll
    for (int pass = 0; pass < 2; pass++) {
        const int idx = t + pass * 256;
        const int g = idx >> 6, o = idx & 63;
        sS[g][o] = scales[(size_t)(gbase + g) * OUTD + obase + o];
        zS[g][o] = zeros[(size_t)(gbase + g) * OUTD + obase + o];
    }

    const int rowA = (lane & 7) + ((lane >> 3) & 1) * 8;
    const int kA   = ((lane >> 4) & 1) * 8;
    const int rowB = (lane & 7) + ((lane >> 4) & 1) * 8;
    const int kB   = ((lane >> 3) & 1) * 8;

    float facc[2][4][4];
    float gacc[2][4][4];
#pragma unroll
    for (int mt = 0; mt < 2; mt++)
#pragma unroll
        for (int ot = 0; ot < 4; ot++)
#pragma unroll
            for (int i = 0; i < 4; i++) { facc[mt][ot][i] = 0.f; gacc[mt][ot][i] = 0.f; }

    // ---- pipeline helpers ----
    auto cpX = [&](int b, int c) {
        const int ck = kq4 * NCH + c;
        const size_t src = ((size_t)ck * MTOT + xrow) * ROWH + xhalf * 32;
        const uint32_t dxh = smb + (b * BUF_H + XH_OFF + xrow * ROWH + xhalf * 32) * 2;
#pragma unroll
        for (int j = 0; j < 4; j++)
            cp16(dxh + j * 16, g_xh + src + j * 8);
        asm volatile("cp.async.commit_group;" ::: "memory");
    };
    auto ldgW = [&](int c, int* qv) {
        const int ck = kq4 * NCH + c;
        const int* Wp = W + (size_t)(ck * KC + skq * 16) * OUTD + obase + so;
#pragma unroll
        for (int p = 0; p < 16; p++) qv[p] = Wp[(size_t)p * OUTD];
    };
    auto stsW = [&](int b, int c, const int* qv) {
        const int z = zS[c >> 1][so];
        uint32_t hp[8];
#pragma unroll
        for (int p = 0; p < 8; p++)
            hp[p] = pack_f16x2((float)(qv[2 * p] - z), (float)(qv[2 * p + 1] - z));
        uint16_t* wq = sm + b * BUF_H + WQ_OFF + so * ROWH + skq * 16;
        ((uint4*)wq)[0] = make_uint4(hp[0], hp[1], hp[2], hp[3]);
        ((uint4*)wq)[1] = make_uint4(hp[4], hp[5], hp[6], hp[7]);
    };

    // lora tiles (needed only by kq4==0 blocks, loaded up front — cheap)
    if (kq4 == 0) {
        ((float4*)sB)[t]        = ((const float4*)(loraB + (size_t)obase * RLORA))[t];
        ((float4*)sxa)[t]       = ((const float4*)g_xa)[t];
        ((float4*)sxa)[t + 256] = ((const float4*)g_xa)[t + 256];
    }

    __syncthreads();   // sS/zS (and lora tiles) ready

    // prologue: chunk 0
    int qv[16];
    ldgW(0, qv);
    cpX(0, 0);
    stsW(0, 0, qv);
    asm volatile("cp.async.wait_group 0;" ::: "memory");
    __syncthreads();

    const int arow = lane >> 2;
    const int acol = (lane & 3) * 2;

    const int aoff0 = XH_OFF + (wm * 32 + 0 * 16 + rowA) * ROWH + kA;
    const int aoff1 = XH_OFF + (wm * 32 + 1 * 16 + rowA) * ROWH + kA;
    const int boff0 = WQ_OFF + (wo * 32 + 0 * 16 + rowB) * ROWH + kB;
    const int boff1 = WQ_OFF + (wo * 32 + 1 * 16 + rowB) * ROWH + kB;

    int buf = 0;
#pragma unroll 1
    for (int c = 0; c < NCH; c++) {
        // issue next chunk's loads early (latency hidden behind MMAs)
        int qn[16];
        if (c + 1 < NCH) {
            ldgW(c + 1, qn);
            cpX(buf ^ 1, c + 1);
        }

        const uint32_t bb = smb + (buf * BUF_H) * 2;
#pragma unroll
        for (int ks = 0; ks < KC; ks += 16) {
            uint32_t a0[4], a1[4], bq0[4], bq1[4];
            ldm4(a0, bb + (aoff0 + ks) * 2);
            ldm4(a1, bb + (aoff1 + ks) * 2);
            ldm4(bq0, bb + (boff0 + ks) * 2);
            ldm4(bq1, bb + (boff1 + ks) * 2);
#pragma unroll
            for (int ot = 0; ot < 4; ot++) {
                const uint32_t b0 = (ot < 2) ? bq0[2 * ot]     : bq1[2 * (ot - 2)];
                const uint32_t b1 = (ot < 2) ? bq0[2 * ot + 1] : bq1[2 * (ot - 2) + 1];
                mma16816(gacc[0][ot], a0, b0, b1);
                mma16816(gacc[1][ot], a1, b0, b1);
            }
        }

        if (c + 1 < NCH) stsW(buf ^ 1, c + 1, qn);

        // fold group scale every 2 chunks (group = 128 k)
        if (c & 1) {
            const int g = c >> 1;
#pragma unroll
            for (int ot = 0; ot < 4; ot++) {
                const float2 sv = *(const float2*)&sS[g][wo * 32 + ot * 8 + acol];
#pragma unroll
                for (int mt = 0; mt < 2; mt++) {
                    facc[mt][ot][0] = fmaf(sv.x, gacc[mt][ot][0], facc[mt][ot][0]);
                    facc[mt][ot][1] = fmaf(sv.y, gacc[mt][ot][1], facc[mt][ot][1]);
                    facc[mt][ot][2] = fmaf(sv.x, gacc[mt][ot][2], facc[mt][ot][2]);
                    facc[mt][ot][3] = fmaf(sv.y, gacc[mt][ot][3], facc[mt][ot][3]);
                    gacc[mt][ot][0] = 0.f; gacc[mt][ot][1] = 0.f;
                    gacc[mt][ot][2] = 0.f; gacc[mt][ot][3] = 0.f;
                }
            }
        }

        asm volatile("cp.async.wait_group 0;" ::: "memory");
        __syncthreads();
        buf ^= 1;
    }

    // ---- LoRA fold (kq4 == 0 blocks only) ----
    if (kq4 == 0) {
#pragma unroll
        for (int mt = 0; mt < 2; mt++)
#pragma unroll
            for (int half = 0; half < 2; half++) {
                const int r = wm * 32 + mt * 16 + half * 8 + arow;
                const float* xr = sxa[r];
#pragma unroll
                for (int ot = 0; ot < 4; ot++) {
                    const int co = wo * 32 + ot * 8 + acol;
                    const float* B0 = sB[co];
                    const float* B1 = sB[co + 1];
                    float l0 = 0.f, l1 = 0.f;
#pragma unroll
                    for (int rr = 0; rr < RLORA; rr++) {
                        l0 = fmaf(xr[rr], B0[rr], l0);
                        l1 = fmaf(xr[rr], B1[rr], l1);
                    }
                    facc[mt][ot][2 * half + 0] += l0;
                    facc[mt][ot][2 * half + 1] += l1;
                }
            }
    }

    // ---- store partials ----
    float* pp = g_partial + (size_t)kq4 * MTOT * OUTD;
#pragma unroll
    for (int mt = 0; mt < 2; mt++) {
        const int r0 = wm * 32 + mt * 16 + arow;
#pragma unroll
        for (int ot = 0; ot < 4; ot++) {
            const int cabs = obase + wo * 32 + ot * 8 + acol;
            *(float2*)&pp[(size_t)r0 * OUTD + cabs] =
                make_float2(facc[mt][ot][0], facc[mt][ot][1]);
            *(float2*)&pp[(size_t)(r0 + 8) * OUTD + cabs] =
                make_float2(facc[mt][ot][2], facc[mt][ot][3]);
        }
    }
}

// ---------------------------------------------------------------------------
// Reduce: pure 4-way partial sum.
// ---------------------------------------------------------------------------
__global__ __launch_bounds__(256) void reduce_kernel(float* __restrict__ out)
{
    const int m = blockIdx.y;
    const int oc = blockIdx.x * 256 + threadIdx.x;
    if (oc >= OUTD / 4) return;
    const int o = 4 * oc;

    float4 s = make_float4(0.f, 0.f, 0.f, 0.f);
#pragma unroll
    for (int p = 0; p < KSPLIT; p++) {
        const float4 v = *(const float4*)&g_partial[(size_t)p * MTOT * OUTD +
                                                    (size_t)m * OUTD + o];
        s.x += v.x; s.y += v.y; s.z += v.z; s.w += v.w;
    }
    *(float4*)&out[(size_t)m * OUTD + o] = s;
}

// ---------------------------------------------------------------------------
extern "C" void kernel_launch(void* const* d_in, const int* in_sizes, int n_in,
                              void* d_out, int out_size) {
    const float* x      = (const float*)d_in[0];
    const int*   W      = (const int*)  d_in[1];
    const int*   zeros  = (const int*)  d_in[2];
    const float* scales = (const float*)d_in[3];
    const float* loraA  = (const float*)d_in[4];
    const float* loraB  = (const float*)d_in[5];
    float* out = (float*)d_out;

    cudaFuncSetAttribute(qmain_kernel,
                         cudaFuncAttributeMaxDynamicSharedMemorySize, SMEM_BYTES);

    zero_xa_kernel<<<2, 1024>>>();

    dim3 pgrid(MTOT, 4);
    prep_kernel<<<pgrid, 256>>>(x, loraA);

    dim3 grid(OUTD / NTILE, KSPLIT);
    qmain_kernel<<<grid, 256, SMEM_BYTES>>>(W, zeros, scales, loraB);

    dim3 rgrid((OUTD / 4 + 255) / 256, MTOT);
    reduce_kernel<<<rgrid, 256>>>(out);
}